// round 4
// baseline (speedup 1.0000x reference)
#include <cuda_runtime.h>
#include <cstdint>

#define T_STEPS 512
#define B_SZ 128
#define I_SZ 256
#define H_SZ 256
#define BH (B_SZ*H_SZ)

typedef unsigned long long ull;

// ---------------- f32x2 helpers ----------------
__device__ __forceinline__ ull pack2(float x, float y) {
    ull r; asm("mov.b64 %0, {%1,%2};" : "=l"(r) : "f"(x), "f"(y)); return r;
}
__device__ __forceinline__ void unpack2(float& x, float& y, ull v) {
    asm("mov.b64 {%0,%1}, %2;" : "=f"(x), "=f"(y) : "l"(v));
}
__device__ __forceinline__ void fma2(ull& d, ull a, ull b) {
    asm("fma.rn.f32x2 %0, %1, %2, %0;" : "+l"(d) : "l"(a), "l"(b));
}
__device__ __forceinline__ ull mul2(ull a, ull b) {
    ull r; asm("mul.rn.f32x2 %0, %1, %2;" : "=l"(r) : "l"(a), "l"(b)); return r;
}

// ---------------- device scratch ----------------
__device__ float d_zx[4*B_SZ*I_SZ];                       // (4,B,I)
__device__ float d_zh[4*B_SZ*H_SZ];                       // (4,B,H)
__device__ float d_xpre[(size_t)T_STEPS*B_SZ*4*H_SZ];     // (T,B,4,H)

// ---------------- masks ----------------
__device__ __forceinline__ float concrete_mask(float u) {
    const float EPSC = 1e-7f;
    float logit_p = logf(0.25f + EPSC) - logf(0.75f + EPSC);
    float lu = logf(u + EPSC) - logf(1.0f - u + EPSC);
    float x = (logit_p + lu) / 0.1f;
    float s = 1.0f / (1.0f + expf(-x));
    return (1.0f - s) / 0.75f;
}

__global__ void mask_kernel(const float* __restrict__ ux, const float* __restrict__ uh) {
    int i = blockIdx.x * blockDim.x + threadIdx.x;
    if (i < 4*B_SZ*I_SZ) {
        d_zx[i] = concrete_mask(ux[i]);
        d_zh[i] = concrete_mask(uh[i]);
    }
}

// ---------------- x_pre GEMM (FFMA2) ----------------
#define XB_BM 128
#define XB_BN 64
#define XB_BK 16

__global__ __launch_bounds__(256) void xpre_kernel(
    const float* __restrict__ input, const float* __restrict__ W, const float* __restrict__ Wb)
{
    __shared__ float As[XB_BK][XB_BM+4];
    __shared__ float Bs[XB_BK][XB_BN+4];
    int g  = blockIdx.z;
    int t  = blockIdx.x;
    int n0 = blockIdx.y * XB_BN;
    int tid = threadIdx.x;
    int tx = tid & 15, ty = tid >> 4;

    ull acc[4][4];
    #pragma unroll
    for (int p = 0; p < 4; p++)
        #pragma unroll
        for (int c = 0; c < 4; c++) acc[p][c] = 0ull;

    const float* inpBase = input + (size_t)t * (B_SZ*I_SZ);
    const float* zxBase  = d_zx + g * (B_SZ*I_SZ);
    const float* wBase   = W + (size_t)g * (H_SZ*I_SZ) + (size_t)n0 * I_SZ;

    int lrow   = tid >> 2;
    int lchunk = (tid & 3) * 4;

    for (int kk0 = 0; kk0 < I_SZ; kk0 += XB_BK) {
        #pragma unroll
        for (int it = 0; it < 2; it++) {
            int row = lrow + it*64;
            float4 av = *(const float4*)(inpBase + row*I_SZ + kk0 + lchunk);
            float4 zv = *(const float4*)(zxBase  + row*I_SZ + kk0 + lchunk);
            As[lchunk+0][row] = av.x*zv.x;
            As[lchunk+1][row] = av.y*zv.y;
            As[lchunk+2][row] = av.z*zv.z;
            As[lchunk+3][row] = av.w*zv.w;
        }
        {
            float4 wv = *(const float4*)(wBase + lrow*I_SZ + kk0 + lchunk);
            Bs[lchunk+0][lrow] = wv.x;
            Bs[lchunk+1][lrow] = wv.y;
            Bs[lchunk+2][lrow] = wv.z;
            Bs[lchunk+3][lrow] = wv.w;
        }
        __syncthreads();
        #pragma unroll
        for (int kk = 0; kk < XB_BK; kk++) {
            float4 b4 = *(const float4*)&Bs[kk][tx*4];
            ulonglong2 a01 = *(const ulonglong2*)&As[kk][ty*8];
            ulonglong2 a23 = *(const ulonglong2*)&As[kk][ty*8+4];
            ull ap[4] = {a01.x, a01.y, a23.x, a23.y};
            ull bb[4] = {pack2(b4.x,b4.x), pack2(b4.y,b4.y),
                         pack2(b4.z,b4.z), pack2(b4.w,b4.w)};
            #pragma unroll
            for (int p = 0; p < 4; p++)
                #pragma unroll
                for (int c = 0; c < 4; c++)
                    fma2(acc[p][c], ap[p], bb[c]);
        }
        __syncthreads();
    }
    float4 wb = *(const float4*)(Wb + g*H_SZ + n0 + tx*4);
    #pragma unroll
    for (int p = 0; p < 4; p++) {
        float lo[4], hi[4];
        #pragma unroll
        for (int c = 0; c < 4; c++) unpack2(lo[c], hi[c], acc[p][c]);
        int b0r = ty*8 + 2*p;
        size_t o0 = (((size_t)t*B_SZ + b0r)*4 + g) * H_SZ + n0 + tx*4;
        size_t o1 = (((size_t)t*B_SZ + b0r+1)*4 + g) * H_SZ + n0 + tx*4;
        *(float4*)(d_xpre + o0) = make_float4(lo[0]+wb.x, lo[1]+wb.y, lo[2]+wb.z, lo[3]+wb.w);
        *(float4*)(d_xpre + o1) = make_float4(hi[0]+wb.x, hi[1]+wb.y, hi[2]+wb.z, hi[3]+wb.w);
    }
}

// ---------------- persistent recurrent kernel (cluster version) ----------------
// 16 clusters x 8 CTAs. Cluster = one b-group of 8 batches; CTA rank = k-split of 32.
// 512 threads. smem: U_s[4][256][32] | zh_s[4][256][10] | hm_s[4][256][10] |
//                    s_s[4q][4g][8b][34] | c_s[256] | ub_s[128]
#define RK_THREADS 512
#define ZST 10
#define SST 34
#define RK_SMEM_FLOATS (4*256*32 + 4*256*ZST + 4*256*ZST + 4*4*8*SST + 256 + 128)
#define RK_SMEM_BYTES (RK_SMEM_FLOATS*4)

__global__ __launch_bounds__(RK_THREADS, 1) __cluster_dims__(8, 1, 1)
void recurrent_kernel(const float* __restrict__ U, const float* __restrict__ Ub,
                      float* __restrict__ out)
{
    extern __shared__ float sm[];
    float* U_s  = sm;                        // 32768
    float* zh_s = U_s  + 4*256*32;           // 10240
    float* hm_s = zh_s + 4*256*ZST;          // 10240
    float* s_s  = hm_s + 4*256*ZST;          // 4352
    float* c_s  = s_s + 4*4*8*SST;           // 256
    float* ub_s = c_s + 256;                 // 128

    int tid = threadIdx.x;
    int bi = blockIdx.x >> 3;  int b0 = bi * 8;      // b-group (cluster id)
    int ki = blockIdx.x & 7;   int k0 = ki * 32;     // k-slice (cluster rank)

    // ---- one-time loads ----
    for (int e = tid; e < 32768; e += RK_THREADS) {      // U_s[(g,h)][k] = U[g,k0+k,h]
        int g = e >> 13; int k = (e >> 8) & 31; int h = e & 255;
        U_s[(g*256 + h)*32 + k] = U[((size_t)(g*H_SZ + k0 + k))*H_SZ + h];
    }
    for (int e = tid; e < 8192; e += RK_THREADS) {       // zh slice (8 b)
        int g = e >> 11; int b = (e >> 8) & 7; int h = e & 255;
        zh_s[(g*256 + h)*ZST + b] = d_zh[((size_t)(g*B_SZ + b0 + b))*H_SZ + h];
    }
    for (int e = tid; e < 4*256*ZST; e += RK_THREADS) hm_s[e] = 0.f;   // t=0: h=0
    if (tid < 128) ub_s[tid] = Ub[(tid >> 5)*H_SZ + k0 + (tid & 31)];
    if (tid < 256) c_s[tid] = 0.f;
    __syncthreads();

    // ---- GEMM warp layout: 16 warps = (q 0..3 h-quarter) x (g 0..3) ----
    int w = tid >> 5, lane = tid & 31;
    int g = w & 3;
    int q = w >> 2;
    int kq = lane & 7;          // 4 k each (2 ull)
    int bg = lane >> 3;         // 0..3, 2 b each
    const float* Ug = U_s  + (g*256 + q*64)*32 + kq*4;
    const float* Hm = hm_s + (g*256 + q*64)*ZST + bg*2;
    float* Sout = s_s + ((q*4 + g)*8 + 2*bg)*SST + kq*4;

    int eb = tid >> 5, ek = tid & 31;   // epilogue cell (b 0..7, k 0..31) for tid<256

    float* hn     = out;
    float* ht_out = out + (size_t)T_STEPS*BH;
    float* ct_out = ht_out + BH;

    // initial x_pre prefetch (t=0)
    float xp0=0, xp1=0, xp2=0, xp3=0;
    if (tid < 256) {
        const float* xpp = d_xpre + (((size_t)(b0 + eb))*4)*H_SZ + k0 + ek;
        xp0 = __ldcs(xpp);
        xp1 = __ldcs(xpp + H_SZ);
        xp2 = __ldcs(xpp + 2*H_SZ);
        xp3 = __ldcs(xpp + 3*H_SZ);
    }

    for (int t = 0; t < T_STEPS; t++) {
        // ---- build hm = h_prev * zh (t>0; t=0 pre-zeroed) ----
        if (t > 0) {
            const float* hprev = hn + (size_t)(t-1)*BH + (size_t)b0*H_SZ;
            #pragma unroll
            for (int i = 0; i < 2; i++) {
                int e = tid + i*RK_THREADS;          // 1024 items: (bpair, h)
                int bp = e >> 8, h = e & 255;
                float h0v = __ldcg(hprev + (2*bp)*H_SZ + h);
                float h1v = __ldcg(hprev + (2*bp+1)*H_SZ + h);
                ull hp = pack2(h0v, h1v);
                #pragma unroll
                for (int gg = 0; gg < 4; gg++) {
                    ull z = *(const ull*)&zh_s[(gg*256+h)*ZST + 2*bp];
                    *(ull*)&hm_s[(gg*256+h)*ZST + 2*bp] = mul2(hp, z);
                }
            }
        }
        __syncthreads();

        // ---- recurrent GEMM: per warp 32k x 8b over its 64-h quarter ----
        {
            ull a00=0ull, a01=0ull, a10=0ull, a11=0ull;
            #pragma unroll 8
            for (int h = 0; h < 64; h++) {
                ulonglong2 u2 = *(const ulonglong2*)(Ug + h*32);
                float2 m = *(const float2*)(Hm + h*ZST);
                ull m0 = pack2(m.x, m.x);
                ull m1 = pack2(m.y, m.y);
                fma2(a00, u2.x, m0);
                fma2(a01, u2.y, m0);
                fma2(a10, u2.x, m1);
                fma2(a11, u2.y, m1);
            }
            *(ull*)(Sout)          = a00;
            *(ull*)(Sout + 2)      = a01;
            *(ull*)(Sout + SST)    = a10;
            *(ull*)(Sout + SST+2)  = a11;
        }
        __syncthreads();

        // ---- epilogue (tid < 256): sum 4 quarters + xpre + Ub, gates, state ----
        if (tid < 256) {
            float s[4];
            #pragma unroll
            for (int gg = 0; gg < 4; gg++) {
                float v = ub_s[gg*32 + ek];
                #pragma unroll
                for (int qq = 0; qq < 4; qq++)
                    v += s_s[((qq*4 + gg)*8 + eb)*SST + ek];
                s[gg] = v;
            }
            s[0] += xp0; s[1] += xp1; s[2] += xp2; s[3] += xp3;
            float iv = __fdividef(1.f, 1.f + __expf(-s[0]));
            float fv = __fdividef(1.f, 1.f + __expf(-s[1]));
            float ov = __fdividef(1.f, 1.f + __expf(-s[2]));
            float gv = __fdividef(2.f, 1.f + __expf(-2.f*s[3])) - 1.f;
            float c  = fv * c_s[tid] + iv * gv;
            c_s[tid] = c;
            float th = __fdividef(2.f, 1.f + __expf(-2.f*c)) - 1.f;
            float hval = ov * th;
            __stcg(&hn[(size_t)t*BH + (b0+eb)*H_SZ + k0+ek], hval);
            if (t == T_STEPS-1) {
                ht_out[(b0+eb)*H_SZ + k0+ek] = hval;
                ct_out[(b0+eb)*H_SZ + k0+ek] = c;
            }
        }

        // ---- cluster barrier (release h writes / acquire peers'), overlap prefetch ----
        if (t < T_STEPS-1) {
            asm volatile("barrier.cluster.arrive.aligned;" ::: "memory");
            if (tid < 256) {
                const float* xpp = d_xpre + (((size_t)(t+1)*B_SZ + b0 + eb)*4)*H_SZ + k0 + ek;
                xp0 = __ldcs(xpp);
                xp1 = __ldcs(xpp + H_SZ);
                xp2 = __ldcs(xpp + 2*H_SZ);
                xp3 = __ldcs(xpp + 3*H_SZ);
            }
            asm volatile("barrier.cluster.wait.aligned;" ::: "memory");
        }
    }
}

// ---------------- launcher ----------------
extern "C" void kernel_launch(void* const* d_in, const int* in_sizes, int n_in,
                              void* d_out, int out_size) {
    const float* input = (const float*)d_in[0];
    const float* ux    = (const float*)d_in[1];
    const float* uh    = (const float*)d_in[2];
    const float* W     = (const float*)d_in[3];
    const float* Wb    = (const float*)d_in[4];
    const float* U     = (const float*)d_in[5];
    const float* Ub    = (const float*)d_in[6];
    float* out = (float*)d_out;

    (void)in_sizes; (void)n_in; (void)out_size;

    cudaFuncSetAttribute(recurrent_kernel,
                         cudaFuncAttributeMaxDynamicSharedMemorySize, RK_SMEM_BYTES);

    mask_kernel<<<512, 256>>>(ux, uh);
    xpre_kernel<<<dim3(T_STEPS, I_SZ/XB_BN, 4), 256>>>(input, W, Wb);
    recurrent_kernel<<<128, RK_THREADS, RK_SMEM_BYTES>>>(U, Ub, out);
}

// round 6
// speedup vs baseline: 1.4101x; 1.4101x over previous
#include <cuda_runtime.h>
#include <cstdint>

#define T_STEPS 512
#define B_SZ 128
#define I_SZ 256
#define H_SZ 256
#define BH (B_SZ*H_SZ)

typedef unsigned long long ull;

// ---------------- f32x2 helpers ----------------
__device__ __forceinline__ ull pack2(float x, float y) {
    ull r; asm("mov.b64 %0, {%1,%2};" : "=l"(r) : "f"(x), "f"(y)); return r;
}
__device__ __forceinline__ void unpack2(float& x, float& y, ull v) {
    asm("mov.b64 {%0,%1}, %2;" : "=f"(x), "=f"(y) : "l"(v));
}
__device__ __forceinline__ void fma2(ull& d, ull a, ull b) {
    asm("fma.rn.f32x2 %0, %1, %2, %0;" : "+l"(d) : "l"(a), "l"(b));
}
__device__ __forceinline__ ull mul2(ull a, ull b) {
    ull r; asm("mul.rn.f32x2 %0, %1, %2;" : "=l"(r) : "l"(a), "l"(b)); return r;
}

// ---------------- device scratch ----------------
__device__ float d_zx[4*B_SZ*I_SZ];                       // (4,B,I)
__device__ float d_zh[4*B_SZ*H_SZ];                       // (4,B,H)
__device__ float d_xpre[(size_t)T_STEPS*B_SZ*4*H_SZ];     // (T,B,4,H)
__device__ unsigned g_bars[8*32];                         // one 128B line per b-group

__global__ void reset_kernel() { if (threadIdx.x < 256) g_bars[threadIdx.x] = 0u; }

// ---------------- masks ----------------
__device__ __forceinline__ float concrete_mask(float u) {
    const float EPSC = 1e-7f;
    float logit_p = logf(0.25f + EPSC) - logf(0.75f + EPSC);
    float lu = logf(u + EPSC) - logf(1.0f - u + EPSC);
    float x = (logit_p + lu) / 0.1f;
    float s = 1.0f / (1.0f + expf(-x));
    return (1.0f - s) / 0.75f;
}

__global__ void mask_kernel(const float* __restrict__ ux, const float* __restrict__ uh) {
    int i = blockIdx.x * blockDim.x + threadIdx.x;
    if (i < 4*B_SZ*I_SZ) {
        d_zx[i] = concrete_mask(ux[i]);
        d_zh[i] = concrete_mask(uh[i]);
    }
}

// ---------------- x_pre GEMM: BK=32, double-buffered ----------------
// x_pre[t,b,g,h] = sum_i input[t,b,i]*zx[g,b,i]*W[g,h,i] + Wb[g,h]
#define XAS 132                       // As row stride (16B-aligned)
#define XBS 68                        // Bs row stride (16B-aligned)
#define XS_FLOATS (2*32*XAS + 2*32*XBS)
#define XS_BYTES  (XS_FLOATS*4)

__global__ __launch_bounds__(256) void xpre_kernel(
    const float* __restrict__ input, const float* __restrict__ W, const float* __restrict__ Wb)
{
    extern __shared__ float xsm[];
    float* As = xsm;                  // [2][32][XAS]
    float* Bs = xsm + 2*32*XAS;       // [2][32][XBS]

    int g  = blockIdx.z;
    int t  = blockIdx.x;              // 128 rows == batches
    int n0 = blockIdx.y * 64;
    int tid = threadIdx.x;
    int tx = tid & 15, ty = tid >> 4;

    ull acc[4][4];
    #pragma unroll
    for (int p = 0; p < 4; p++)
        #pragma unroll
        for (int c = 0; c < 4; c++) acc[p][c] = 0ull;

    const float* inpBase = input + (size_t)t * (B_SZ*I_SZ);
    const float* zxBase  = d_zx + g * (B_SZ*I_SZ);
    const float* wBase   = W + (size_t)g * (H_SZ*I_SZ) + (size_t)n0 * I_SZ;

    int arow = tid >> 1;              // 0..127
    int acol = (tid & 1) * 16;        // 0 / 16
    int brow = tid >> 2;              // 0..63
    int bcol = (tid & 3) * 8;         // 0,8,16,24

    float4 aA[4], aZ[4], bW[2];

    // prologue: load stage 0
    #pragma unroll
    for (int j = 0; j < 4; j++) {
        aA[j] = *(const float4*)(inpBase + arow*I_SZ + acol + j*4);
        aZ[j] = *(const float4*)(zxBase  + arow*I_SZ + acol + j*4);
    }
    #pragma unroll
    for (int j = 0; j < 2; j++)
        bW[j] = *(const float4*)(wBase + brow*I_SZ + bcol + j*4);
    #pragma unroll
    for (int j = 0; j < 4; j++) {
        int kc = acol + j*4;
        As[(0*32 + kc+0)*XAS + arow] = aA[j].x*aZ[j].x;
        As[(0*32 + kc+1)*XAS + arow] = aA[j].y*aZ[j].y;
        As[(0*32 + kc+2)*XAS + arow] = aA[j].z*aZ[j].z;
        As[(0*32 + kc+3)*XAS + arow] = aA[j].w*aZ[j].w;
    }
    #pragma unroll
    for (int j = 0; j < 2; j++) {
        int kc = bcol + j*4;
        Bs[(0*32 + kc+0)*XBS + brow] = bW[j].x;
        Bs[(0*32 + kc+1)*XBS + brow] = bW[j].y;
        Bs[(0*32 + kc+2)*XBS + brow] = bW[j].z;
        Bs[(0*32 + kc+3)*XBS + brow] = bW[j].w;
    }
    __syncthreads();

    for (int s = 0; s < 8; s++) {
        if (s < 7) {                  // prefetch next stage into registers
            int k0 = (s+1)*32;
            #pragma unroll
            for (int j = 0; j < 4; j++) {
                aA[j] = *(const float4*)(inpBase + arow*I_SZ + k0 + acol + j*4);
                aZ[j] = *(const float4*)(zxBase  + arow*I_SZ + k0 + acol + j*4);
            }
            #pragma unroll
            for (int j = 0; j < 2; j++)
                bW[j] = *(const float4*)(wBase + brow*I_SZ + k0 + bcol + j*4);
        }
        const float* Ab = As + (s & 1)*32*XAS;
        const float* Bb = Bs + (s & 1)*32*XBS;
        #pragma unroll
        for (int kk = 0; kk < 32; kk++) {
            float4 b4 = *(const float4*)&Bb[kk*XBS + tx*4];
            ulonglong2 a01 = *(const ulonglong2*)&Ab[kk*XAS + ty*8];
            ulonglong2 a23 = *(const ulonglong2*)&Ab[kk*XAS + ty*8+4];
            ull ap[4] = {a01.x, a01.y, a23.x, a23.y};
            ull bb[4] = {pack2(b4.x,b4.x), pack2(b4.y,b4.y),
                         pack2(b4.z,b4.z), pack2(b4.w,b4.w)};
            #pragma unroll
            for (int p = 0; p < 4; p++)
                #pragma unroll
                for (int c = 0; c < 4; c++)
                    fma2(acc[p][c], ap[p], bb[c]);
        }
        if (s < 7) {
            __syncthreads();
            int nb = (s+1) & 1;
            #pragma unroll
            for (int j = 0; j < 4; j++) {
                int kc = acol + j*4;
                As[(nb*32 + kc+0)*XAS + arow] = aA[j].x*aZ[j].x;
                As[(nb*32 + kc+1)*XAS + arow] = aA[j].y*aZ[j].y;
                As[(nb*32 + kc+2)*XAS + arow] = aA[j].z*aZ[j].z;
                As[(nb*32 + kc+3)*XAS + arow] = aA[j].w*aZ[j].w;
            }
            #pragma unroll
            for (int j = 0; j < 2; j++) {
                int kc = bcol + j*4;
                Bs[(nb*32 + kc+0)*XBS + brow] = bW[j].x;
                Bs[(nb*32 + kc+1)*XBS + brow] = bW[j].y;
                Bs[(nb*32 + kc+2)*XBS + brow] = bW[j].z;
                Bs[(nb*32 + kc+3)*XBS + brow] = bW[j].w;
            }
            __syncthreads();
        }
    }

    float4 wb = *(const float4*)(Wb + g*H_SZ + n0 + tx*4);
    #pragma unroll
    for (int p = 0; p < 4; p++) {
        float lo[4], hi[4];
        #pragma unroll
        for (int c = 0; c < 4; c++) unpack2(lo[c], hi[c], acc[p][c]);
        int b0r = ty*8 + 2*p;
        size_t o0 = (((size_t)t*B_SZ + b0r)*4 + g) * H_SZ + n0 + tx*4;
        size_t o1 = (((size_t)t*B_SZ + b0r+1)*4 + g) * H_SZ + n0 + tx*4;
        *(float4*)(d_xpre + o0) = make_float4(lo[0]+wb.x, lo[1]+wb.y, lo[2]+wb.z, lo[3]+wb.w);
        *(float4*)(d_xpre + o1) = make_float4(hi[0]+wb.x, hi[1]+wb.y, hi[2]+wb.z, hi[3]+wb.w);
    }
}

// ---------------- persistent recurrent kernel ----------------
// 128 CTAs (8 b-groups x 16 k-CTAs), 512 threads, padded atomic barrier per b-group.
// smem floats: U_s[4][256][16] | zh_s[4][256][18] | hm_s[4][256][18] |
//              s_s[4q][4g][16b][17] | c_s[256] | ub_s[64]
#define RK_THREADS 512
#define ZST 18
#define SST 17
#define RK_SMEM_FLOATS (4*256*16 + 4*256*ZST + 4*256*ZST + 4*4*16*SST + 256 + 64)
#define RK_SMEM_BYTES (RK_SMEM_FLOATS*4)

__global__ __launch_bounds__(RK_THREADS, 1) void recurrent_kernel(
    const float* __restrict__ U, const float* __restrict__ Ub, float* __restrict__ out)
{
    extern __shared__ float sm[];
    float* U_s  = sm;                        // 16384
    float* zh_s = U_s  + 4*256*16;           // 18432
    float* hm_s = zh_s + 4*256*ZST;          // 18432
    float* s_s  = hm_s + 4*256*ZST;          // 4352
    float* c_s  = s_s + 4*4*16*SST;          // 256
    float* ub_s = c_s + 256;                 // 64

    int tid = threadIdx.x;
    int bi = blockIdx.x >> 4;  int b0 = bi * 16;
    int ki = blockIdx.x & 15;  int k0 = ki * 16;

    // ---- one-time loads ----
    for (int e = tid; e < 16384; e += RK_THREADS) {       // U_s[(g,h)][k] = U[g,k0+k,h]
        int g = e >> 12; int k = (e >> 8) & 15; int h = e & 255;
        U_s[(g*256 + h)*16 + k] = U[((size_t)(g*H_SZ + k0 + k))*H_SZ + h];
    }
    for (int e = tid; e < 16384; e += RK_THREADS) {       // zh slice
        int g = e >> 12; int b = (e >> 8) & 15; int h = e & 255;
        zh_s[(g*256 + h)*ZST + b] = d_zh[((size_t)(g*B_SZ + b0 + b))*H_SZ + h];
    }
    for (int e = tid; e < 4*256*ZST; e += RK_THREADS) hm_s[e] = 0.f;   // t=0 state
    if (tid < 64) ub_s[tid] = Ub[(tid >> 4)*H_SZ + k0 + (tid & 15)];
    if (tid < 256) c_s[tid] = 0.f;
    __syncthreads();

    // ---- GEMM warp layout: 16 warps = (q 0..3 h-quarter) x (g 0..3) ----
    int w = tid >> 5, lane = tid & 31;
    int g = w & 3;
    int q = w >> 2;
    int kq = lane & 3;           // 4 k each
    int bg = lane >> 2;          // 0..7, 2 b each
    const float* Ug  = U_s  + (g*256 + q*64)*16 + kq*4;
    const float* HmP = hm_s + (g*256 + q*64)*ZST + bg*2;
    float* Sout = s_s + ((q*4 + g)*16 + 2*bg)*SST + kq*4;

    int eb = tid >> 4, ek = tid & 15;   // epilogue cell (valid for tid<256)

    float* hn     = out;
    float* ht_out = out + (size_t)T_STEPS*BH;
    float* ct_out = ht_out + BH;

    unsigned* mybar = &g_bars[bi*32];

    // initial x_pre prefetch (t=0)
    float xp0=0, xp1=0, xp2=0, xp3=0;
    if (tid < 256) {
        const float* xpp = d_xpre + (((size_t)(b0 + eb))*4)*H_SZ + k0 + ek;
        xp0 = __ldcs(xpp);
        xp1 = __ldcs(xpp + H_SZ);
        xp2 = __ldcs(xpp + 2*H_SZ);
        xp3 = __ldcs(xpp + 3*H_SZ);
    }

    for (int t = 0; t < T_STEPS; t++) {
        // ---- build hm = h_prev * zh (t=0 pre-zeroed) ----
        if (t > 0) {
            const float* hprev = hn + (size_t)(t-1)*BH + (size_t)b0*H_SZ;
            float hv0[4], hv1[4];
            #pragma unroll
            for (int i = 0; i < 4; i++) {
                int e = tid + i*RK_THREADS;       // (bp 0..7, h 0..255)
                int bp = e >> 8, h = e & 255;
                hv0[i] = __ldcg(hprev + (2*bp)*H_SZ + h);
                hv1[i] = __ldcg(hprev + (2*bp+1)*H_SZ + h);
            }
            #pragma unroll
            for (int i = 0; i < 4; i++) {
                int e = tid + i*RK_THREADS;
                int bp = e >> 8, h = e & 255;
                ull hp = pack2(hv0[i], hv1[i]);
                #pragma unroll
                for (int gg = 0; gg < 4; gg++) {
                    ull z = *(const ull*)&zh_s[(gg*256+h)*ZST + 2*bp];
                    *(ull*)&hm_s[(gg*256+h)*ZST + 2*bp] = mul2(hp, z);
                }
            }
        }
        __syncthreads();

        // ---- recurrent GEMM: per warp 16k x 16b over 64-h quarter ----
        {
            ull a00=0ull, a01=0ull, a10=0ull, a11=0ull;
            #pragma unroll 8
            for (int h = 0; h < 64; h++) {
                ulonglong2 u2 = *(const ulonglong2*)(Ug + h*16);
                float2 m = *(const float2*)(HmP + h*ZST);
                ull m0 = pack2(m.x, m.x);
                ull m1 = pack2(m.y, m.y);
                fma2(a00, u2.x, m0);
                fma2(a01, u2.y, m0);
                fma2(a10, u2.x, m1);
                fma2(a11, u2.y, m1);
            }
            *(ull*)(Sout)     = a00;        // b even row (even float offset)
            *(ull*)(Sout + 2) = a01;
            float lo, hi;                   // b odd row has odd offset -> scalar
            unpack2(lo, hi, a10); Sout[SST]   = lo; Sout[SST+1] = hi;
            unpack2(lo, hi, a11); Sout[SST+2] = lo; Sout[SST+3] = hi;
        }
        __syncthreads();

        // ---- epilogue (tid < 256) ----
        if (tid < 256) {
            float s[4];
            #pragma unroll
            for (int gg = 0; gg < 4; gg++) {
                float v = ub_s[gg*16 + ek];
                #pragma unroll
                for (int qq = 0; qq < 4; qq++)
                    v += s_s[((qq*4 + gg)*16 + eb)*SST + ek];
                s[gg] = v;
            }
            s[0] += xp0; s[1] += xp1; s[2] += xp2; s[3] += xp3;
            float iv = __fdividef(1.f, 1.f + __expf(-s[0]));
            float fv = __fdividef(1.f, 1.f + __expf(-s[1]));
            float ov = __fdividef(1.f, 1.f + __expf(-s[2]));
            float gv = __fdividef(2.f, 1.f + __expf(-2.f*s[3])) - 1.f;
            float c  = fv * c_s[tid] + iv * gv;
            c_s[tid] = c;
            float th = __fdividef(2.f, 1.f + __expf(-2.f*c)) - 1.f;
            float hval = ov * th;
            __stcg(&hn[(size_t)t*BH + (b0+eb)*H_SZ + k0+ek], hval);
            if (t == T_STEPS-1) {
                ht_out[(b0+eb)*H_SZ + k0+ek] = hval;
                ct_out[(b0+eb)*H_SZ + k0+ek] = c;
            }
        }
        __threadfence();
        __syncthreads();

        // ---- per-b-group barrier (16 CTAs, padded counter) ----
        if (t < T_STEPS-1) {
            if (tid == 0) {
                atomicAdd(mybar, 1u);
                unsigned target = (unsigned)(t+1) * 16u;
                while (*(volatile unsigned*)mybar < target) { }
            }
            __syncthreads();
            // prefetch next step's x_pre (overlaps next hm build)
            if (tid < 256) {
                const float* xpp = d_xpre + (((size_t)(t+1)*B_SZ + b0 + eb)*4)*H_SZ + k0 + ek;
                xp0 = __ldcs(xpp);
                xp1 = __ldcs(xpp + H_SZ);
                xp2 = __ldcs(xpp + 2*H_SZ);
                xp3 = __ldcs(xpp + 3*H_SZ);
            }
        }
    }
}

// ---------------- launcher ----------------
extern "C" void kernel_launch(void* const* d_in, const int* in_sizes, int n_in,
                              void* d_out, int out_size) {
    const float* input = (const float*)d_in[0];
    const float* ux    = (const float*)d_in[1];
    const float* uh    = (const float*)d_in[2];
    const float* W     = (const float*)d_in[3];
    const float* Wb    = (const float*)d_in[4];
    const float* U     = (const float*)d_in[5];
    const float* Ub    = (const float*)d_in[6];
    float* out = (float*)d_out;

    (void)in_sizes; (void)n_in; (void)out_size;

    cudaFuncSetAttribute(recurrent_kernel,
                         cudaFuncAttributeMaxDynamicSharedMemorySize, RK_SMEM_BYTES);
    cudaFuncSetAttribute(xpre_kernel,
                         cudaFuncAttributeMaxDynamicSharedMemorySize, XS_BYTES);

    reset_kernel<<<1, 256>>>();
    mask_kernel<<<512, 256>>>(ux, uh);
    xpre_kernel<<<dim3(T_STEPS, 4, 4), 256, XS_BYTES>>>(input, W, Wb);
    recurrent_kernel<<<128, RK_THREADS, RK_SMEM_BYTES>>>(U, Ub, out);
}

// round 11
// speedup vs baseline: 1.6565x; 1.1748x over previous
#include <cuda_runtime.h>
#include <cstdint>

#define T_STEPS 512
#define B_SZ 128
#define I_SZ 256
#define H_SZ 256
#define BH (B_SZ*H_SZ)

typedef unsigned long long ull;

// ---------------- f32x2 helpers ----------------
__device__ __forceinline__ ull pack2(float x, float y) {
    ull r; asm("mov.b64 %0, {%1,%2};" : "=l"(r) : "f"(x), "f"(y)); return r;
}
__device__ __forceinline__ void unpack2(float& x, float& y, ull v) {
    asm("mov.b64 {%0,%1}, %2;" : "=f"(x), "=f"(y) : "l"(v));
}
__device__ __forceinline__ void fma2(ull& d, ull a, ull b) {
    asm("fma.rn.f32x2 %0, %1, %2, %0;" : "+l"(d) : "l"(a), "l"(b));
}
__device__ __forceinline__ ull mul2(ull a, ull b) {
    ull r; asm("mul.rn.f32x2 %0, %1, %2;" : "=l"(r) : "l"(a), "l"(b)); return r;
}

// ---------------- device scratch ----------------
__device__ float d_zx[4*B_SZ*I_SZ];                       // (4,B,I)
__device__ float d_zh[4*B_SZ*H_SZ];                       // (4,B,H)
__device__ float d_xpre[(size_t)T_STEPS*B_SZ*4*H_SZ];     // (T,B,4,H)
__device__ unsigned g_bars[8*32];                         // one 128B line per b-group

__global__ void reset_kernel() { if (threadIdx.x < 256) g_bars[threadIdx.x] = 0u; }

// ---------------- masks ----------------
__device__ __forceinline__ float concrete_mask(float u) {
    const float EPSC = 1e-7f;
    float logit_p = logf(0.25f + EPSC) - logf(0.75f + EPSC);
    float lu = logf(u + EPSC) - logf(1.0f - u + EPSC);
    float x = (logit_p + lu) / 0.1f;
    float s = 1.0f / (1.0f + expf(-x));
    return (1.0f - s) / 0.75f;
}

__global__ void mask_kernel(const float* __restrict__ ux, const float* __restrict__ uh) {
    int i = blockIdx.x * blockDim.x + threadIdx.x;
    if (i < 4*B_SZ*I_SZ) {
        d_zx[i] = concrete_mask(ux[i]);
        d_zh[i] = concrete_mask(uh[i]);
    }
}

// ---------------- x_pre GEMM (BK=16, FFMA2) ----------------
#define XB_BM 128
#define XB_BN 64
#define XB_BK 16

__global__ __launch_bounds__(256) void xpre_kernel(
    const float* __restrict__ input, const float* __restrict__ W, const float* __restrict__ Wb)
{
    __shared__ float As[XB_BK][XB_BM+4];
    __shared__ float Bs[XB_BK][XB_BN+4];
    int g  = blockIdx.z;
    int t  = blockIdx.x;
    int n0 = blockIdx.y * XB_BN;
    int tid = threadIdx.x;
    int tx = tid & 15, ty = tid >> 4;

    ull acc[4][4];
    #pragma unroll
    for (int p = 0; p < 4; p++)
        #pragma unroll
        for (int c = 0; c < 4; c++) acc[p][c] = 0ull;

    const float* inpBase = input + (size_t)t * (B_SZ*I_SZ);
    const float* zxBase  = d_zx + g * (B_SZ*I_SZ);
    const float* wBase   = W + (size_t)g * (H_SZ*I_SZ) + (size_t)n0 * I_SZ;

    int lrow   = tid >> 2;
    int lchunk = (tid & 3) * 4;

    for (int kk0 = 0; kk0 < I_SZ; kk0 += XB_BK) {
        #pragma unroll
        for (int it = 0; it < 2; it++) {
            int row = lrow + it*64;
            float4 av = *(const float4*)(inpBase + row*I_SZ + kk0 + lchunk);
            float4 zv = *(const float4*)(zxBase  + row*I_SZ + kk0 + lchunk);
            As[lchunk+0][row] = av.x*zv.x;
            As[lchunk+1][row] = av.y*zv.y;
            As[lchunk+2][row] = av.z*zv.z;
            As[lchunk+3][row] = av.w*zv.w;
        }
        {
            float4 wv = *(const float4*)(wBase + lrow*I_SZ + kk0 + lchunk);
            Bs[lchunk+0][lrow] = wv.x;
            Bs[lchunk+1][lrow] = wv.y;
            Bs[lchunk+2][lrow] = wv.z;
            Bs[lchunk+3][lrow] = wv.w;
        }
        __syncthreads();
        #pragma unroll
        for (int kk = 0; kk < XB_BK; kk++) {
            float4 b4 = *(const float4*)&Bs[kk][tx*4];
            ulonglong2 a01 = *(const ulonglong2*)&As[kk][ty*8];
            ulonglong2 a23 = *(const ulonglong2*)&As[kk][ty*8+4];
            ull ap[4] = {a01.x, a01.y, a23.x, a23.y};
            ull bb[4] = {pack2(b4.x,b4.x), pack2(b4.y,b4.y),
                         pack2(b4.z,b4.z), pack2(b4.w,b4.w)};
            #pragma unroll
            for (int p = 0; p < 4; p++)
                #pragma unroll
                for (int c = 0; c < 4; c++)
                    fma2(acc[p][c], ap[p], bb[c]);
        }
        __syncthreads();
    }
    float4 wb = *(const float4*)(Wb + g*H_SZ + n0 + tx*4);
    #pragma unroll
    for (int p = 0; p < 4; p++) {
        float lo[4], hi[4];
        #pragma unroll
        for (int c = 0; c < 4; c++) unpack2(lo[c], hi[c], acc[p][c]);
        int b0r = ty*8 + 2*p;
        size_t o0 = (((size_t)t*B_SZ + b0r)*4 + g) * H_SZ + n0 + tx*4;
        size_t o1 = (((size_t)t*B_SZ + b0r+1)*4 + g) * H_SZ + n0 + tx*4;
        *(float4*)(d_xpre + o0) = make_float4(lo[0]+wb.x, lo[1]+wb.y, lo[2]+wb.z, lo[3]+wb.w);
        *(float4*)(d_xpre + o1) = make_float4(hi[0]+wb.x, hi[1]+wb.y, hi[2]+wb.z, hi[3]+wb.w);
    }
}

// ---------------- persistent recurrent kernel ----------------
// 128 CTAs (8 b-groups x 16 k-CTAs), 256 threads.
// smem: U_s[16 qg-blocks][UQB] | hm_s[16 qg-blocks][HQB] | s_s[4q][4g][16k][SST] | c_s[256]
// zh in registers. Barrier: syncthreads + tid0 red.release.gpu / ld.acquire.gpu.
#define RK_THREADS 256
#define UQB 1032                     // 64*16 + 8 (quarter skew)
#define HQB 1160                     // 64*18 + 8 (quarter skew)
#define SST 20                       // 80 B row stride -> float4 stays 16B-aligned
#define RK_SMEM_FLOATS (16*UQB + 16*HQB + 4*4*16*SST + 256)
#define RK_SMEM_BYTES (RK_SMEM_FLOATS*4)

__global__ __launch_bounds__(RK_THREADS, 1) void recurrent_kernel(
    const float* __restrict__ U, const float* __restrict__ Ub, float* __restrict__ out)
{
    extern __shared__ float sm[];
    float* U_s  = sm;                        // 16*1032 = 16512
    float* hm_s = U_s + 16*UQB;              // 16*1160 = 18560
    float* s_s  = hm_s + 16*HQB;             // 4*4*16*20 = 5120
    float* c_s  = s_s + 4*4*16*SST;          // 256

    int tid = threadIdx.x;
    int bi = blockIdx.x >> 4;  int b0 = bi * 16;
    int ki = blockIdx.x & 15;  int k0 = ki * 16;

    // ---- one-time loads ----
    for (int e = tid; e < 16384; e += RK_THREADS) {       // U_s[(g,hq)][h_in*16+k] = U[g,k0+k,h]
        int g = e >> 12; int k = (e >> 8) & 15; int h = e & 255;
        U_s[(g*4 + (h >> 6))*UQB + (h & 63)*16 + k] =
            U[((size_t)(g*H_SZ + k0 + k))*H_SZ + h];
    }
    for (int e = tid; e < 16*HQB; e += RK_THREADS) hm_s[e] = 0.f;   // t=0 state
    c_s[tid] = 0.f;

    // zh registers: thread h=tid, zr[g][bp] packs batches (2bp, 2bp+1)
    ull zr[4][8];
    {
        int h = tid;
        #pragma unroll
        for (int g = 0; g < 4; g++)
            #pragma unroll
            for (int bp = 0; bp < 8; bp++) {
                float z0 = d_zh[((size_t)(g*B_SZ + b0 + 2*bp))*H_SZ + h];
                float z1 = d_zh[((size_t)(g*B_SZ + b0 + 2*bp+1))*H_SZ + h];
                zr[g][bp] = pack2(z0, z1);
            }
    }

    int eb = tid >> 4, ek = tid & 15;   // epilogue cell (b,k)
    float ubr[4];
    #pragma unroll
    for (int g = 0; g < 4; g++) ubr[g] = Ub[g*H_SZ + k0 + ek];
    __syncthreads();

    // ---- GEMM layout: 8 warps = (hH 0..1) x (g 0..3); lane = (hq2, bq, kq) ----
    int w = tid >> 5, lane = tid & 31;
    int g   = w & 3;
    int hH  = w >> 2;
    int kq  = lane & 3;
    int bq  = (lane >> 2) & 3;
    int hq  = hH*2 + (lane >> 4);
    const float* Ug = U_s  + (g*4 + hq)*UQB + kq*4;
    const float* Hm = hm_s + (g*4 + hq)*HQB + 4*bq;
    float* Sbase = s_s + ((hq*4 + g)*16 + kq*4)*SST + 4*bq;

    float* hn     = out;
    float* ht_out = out + (size_t)T_STEPS*BH;
    float* ct_out = ht_out + BH;

    unsigned* mybar = &g_bars[bi*32];

    // initial x_pre prefetch (t=0)
    const float* xpp = d_xpre + (((size_t)(b0 + eb))*4)*H_SZ + k0 + ek;
    float xp0 = __ldcs(xpp);
    float xp1 = __ldcs(xpp + H_SZ);
    float xp2 = __ldcs(xpp + 2*H_SZ);
    float xp3 = __ldcs(xpp + 3*H_SZ);

    for (int t = 0; t < T_STEPS; t++) {
        // ---- build hm = h_prev * zh (t=0 pre-zeroed) ----
        if (t > 0) {
            const float* hprev = hn + (size_t)(t-1)*BH + (size_t)b0*H_SZ;
            int h = tid;
            int hqi = h >> 6, h_in = h & 63;
            float hv0[8], hv1[8];
            #pragma unroll
            for (int bp = 0; bp < 8; bp++) {
                hv0[bp] = __ldcg(hprev + (2*bp)*H_SZ + h);
                hv1[bp] = __ldcg(hprev + (2*bp+1)*H_SZ + h);
            }
            #pragma unroll
            for (int bp = 0; bp < 8; bp++) {
                ull hp = pack2(hv0[bp], hv1[bp]);
                #pragma unroll
                for (int gg = 0; gg < 4; gg++)
                    *(ull*)&hm_s[(gg*4 + hqi)*HQB + h_in*18 + 2*bp] = mul2(hp, zr[gg][bp]);
            }
        }
        __syncthreads();

        // ---- recurrent GEMM: per thread 4k x 4b over 64 h ----
        {
            ull a0[2] = {0ull,0ull}, a1[2] = {0ull,0ull};
            ull a2[2] = {0ull,0ull}, a3[2] = {0ull,0ull};
            #pragma unroll 8
            for (int h = 0; h < 64; h++) {
                ulonglong2 u2 = *(const ulonglong2*)(Ug + h*16);
                float2 mA = *(const float2*)(Hm + h*18);
                float2 mB = *(const float2*)(Hm + h*18 + 2);
                ull m0 = pack2(mA.x, mA.x);
                ull m1 = pack2(mA.y, mA.y);
                ull m2 = pack2(mB.x, mB.x);
                ull m3 = pack2(mB.y, mB.y);
                fma2(a0[0], u2.x, m0); fma2(a0[1], u2.y, m0);
                fma2(a1[0], u2.x, m1); fma2(a1[1], u2.y, m1);
                fma2(a2[0], u2.x, m2); fma2(a2[1], u2.y, m2);
                fma2(a3[0], u2.x, m3); fma2(a3[1], u2.y, m3);
            }
            float f0[4], f1[4], f2[4], f3[4];
            unpack2(f0[0], f0[1], a0[0]); unpack2(f0[2], f0[3], a0[1]);
            unpack2(f1[0], f1[1], a1[0]); unpack2(f1[2], f1[3], a1[1]);
            unpack2(f2[0], f2[1], a2[0]); unpack2(f2[2], f2[3], a2[1]);
            unpack2(f3[0], f3[1], a3[0]); unpack2(f3[2], f3[3], a3[1]);
            #pragma unroll
            for (int kk = 0; kk < 4; kk++)
                *(float4*)(Sbase + kk*SST) = make_float4(f0[kk], f1[kk], f2[kk], f3[kk]);
        }
        __syncthreads();

        // ---- epilogue: sum 4 quarters + xpre + Ub, gates, state ----
        {
            float s[4];
            #pragma unroll
            for (int gg = 0; gg < 4; gg++) {
                float v = ubr[gg];
                #pragma unroll
                for (int qq = 0; qq < 4; qq++)
                    v += s_s[((qq*4 + gg)*16 + ek)*SST + eb];
                s[gg] = v;
            }
            s[0] += xp0; s[1] += xp1; s[2] += xp2; s[3] += xp3;
            float iv = __fdividef(1.f, 1.f + __expf(-s[0]));
            float fv = __fdividef(1.f, 1.f + __expf(-s[1]));
            float ov = __fdividef(1.f, 1.f + __expf(-s[2]));
            float gv = __fdividef(2.f, 1.f + __expf(-2.f*s[3])) - 1.f;
            float c  = fv * c_s[tid] + iv * gv;
            c_s[tid] = c;
            float th = __fdividef(2.f, 1.f + __expf(-2.f*c)) - 1.f;
            float hval = ov * th;
            __stcg(&hn[(size_t)t*BH + (b0+eb)*H_SZ + k0+ek], hval);
            if (t == T_STEPS-1) {
                ht_out[(b0+eb)*H_SZ + k0+ek] = hval;
                ct_out[(b0+eb)*H_SZ + k0+ek] = c;
            }
        }

        if (t < T_STEPS-1) {
            // prefetch next step's x_pre (independent of barrier; hides under poll)
            const float* xpn = d_xpre + (((size_t)(t+1)*B_SZ + b0 + eb)*4)*H_SZ + k0 + ek;
            xp0 = __ldcs(xpn);
            xp1 = __ldcs(xpn + H_SZ);
            xp2 = __ldcs(xpn + 2*H_SZ);
            xp3 = __ldcs(xpn + 3*H_SZ);

            // ---- barrier: CTA-publish via syncthreads + single release-add ----
            __syncthreads();
            if (tid == 0) {
                asm volatile("red.release.gpu.add.u32 [%0], %1;"
                             :: "l"(mybar), "r"(1u) : "memory");
                unsigned target = (unsigned)(t+1) * 16u;
                unsigned v;
                do {
                    asm volatile("ld.acquire.gpu.u32 %0, [%1];" : "=r"(v) : "l"(mybar));
                } while (v < target);
            }
            __syncthreads();
        }
    }
}

// ---------------- launcher ----------------
extern "C" void kernel_launch(void* const* d_in, const int* in_sizes, int n_in,
                              void* d_out, int out_size) {
    const float* input = (const float*)d_in[0];
    const float* ux    = (const float*)d_in[1];
    const float* uh    = (const float*)d_in[2];
    const float* W     = (const float*)d_in[3];
    const float* Wb    = (const float*)d_in[4];
    const float* U     = (const float*)d_in[5];
    const float* Ub    = (const float*)d_in[6];
    float* out = (float*)d_out;

    (void)in_sizes; (void)n_in; (void)out_size;

    cudaFuncSetAttribute(recurrent_kernel,
                         cudaFuncAttributeMaxDynamicSharedMemorySize, RK_SMEM_BYTES);

    reset_kernel<<<1, 256>>>();
    mask_kernel<<<512, 256>>>(ux, uh);
    xpre_kernel<<<dim3(T_STEPS, 4, 4), 256>>>(input, W, Wb);
    recurrent_kernel<<<128, RK_THREADS, RK_SMEM_BYTES>>>(U, Ub, out);
}